// round 3
// baseline (speedup 1.0000x reference)
#include <cuda_runtime.h>

#define N_NODES 50000
#define N_EDGES 1600000
#define ND 64
#define HD 128
#define ED 32
#define MI 160
#define EB 8
#define NWARPS 8
#define THREADS (NWARPS * 32)
#define PAD1 164
#define PAD2 132
#define FULLMASK 0xffffffffu

// Scratch (no cudaMalloc allowed): packed int32 edge indices + dtype flag.
__device__ int g_is64;
__device__ int g_src[N_EDGES];
__device__ int g_dst[N_EDGES];

// ---------------------------------------------------------------------------
__global__ void detect_kernel(const unsigned int* __restrict__ w) {
    if (blockIdx.x == 0 && threadIdx.x == 0) {
        int is64 = 1;
        for (int i = 0; i < 64; i++) {
            if (w[2 * i + 1] != 0u) { is64 = 0; break; }
        }
        g_is64 = is64;
    }
}

__global__ void convert_kernel(const void* __restrict__ p) {
    int i = blockIdx.x * blockDim.x + threadIdx.x;
    if (i >= N_EDGES) return;
    if (g_is64) {
        const long long* q = (const long long*)p;
        g_src[i] = (int)q[i];
        g_dst[i] = (int)q[N_EDGES + i];
    } else {
        const int* q = (const int*)p;
        g_src[i] = q[i];
        g_dst[i] = q[N_EDGES + i];
    }
}

// out = [h (N*64) | x (N*3)], initialized with the residual inputs.
__global__ void init_out_kernel(const float* __restrict__ h,
                                const float* __restrict__ x,
                                float* __restrict__ out) {
    int i = blockIdx.x * blockDim.x + threadIdx.x;
    const int nh = N_NODES * ND;
    const int total = nh + N_NODES * 3;
    if (i < nh) out[i] = h[i];
    else if (i < total) out[i] = x[i - nh];
}

__device__ __forceinline__ float silu(float v) {
    return __fdividef(v, 1.0f + __expf(-v));
}

// ---------------------------------------------------------------------------
// Persistent grid, 1 CTA/SM, 8 warps, 8 edges per warp-task.
// W1 (node & coord) stored transposed+padded in smem so each lane fetches its
// 4 output-weights for 4 consecutive k as float4 LDS.128 (conflict-free per
// quarter-warp). m_input lives in registers; k-broadcast via shfl.
// ---------------------------------------------------------------------------
__global__ void __launch_bounds__(THREADS, 1)
edge_kernel(const float* __restrict__ h, const float* __restrict__ x,
            const float* __restrict__ edge_dist,
            const float* __restrict__ node_w1, const float* __restrict__ node_b1,
            const float* __restrict__ node_w2, const float* __restrict__ node_b2,
            const float* __restrict__ coord_w1, const float* __restrict__ coord_b1,
            const float* __restrict__ coord_w2,
            const float* __restrict__ edge_w1, const float* __restrict__ edge_b1,
            const float* __restrict__ edge_w2, const float* __restrict__ edge_b2,
            float* __restrict__ out) {
    extern __shared__ float smem[];
    float* s_nw1t = smem;                    // 128 * 164
    float* s_cw1t = s_nw1t + HD * PAD1;      // 128 * 164
    float* s_nw2t = s_cw1t + HD * PAD1;      // 64 * 132
    float* s_ew2  = s_nw2t + ND * PAD2;      // 32 * 32
    float* s_cw2  = s_ew2 + ED * ED;         // 128
    float* s_nb1  = s_cw2 + HD;              // 128
    float* s_cb1  = s_nb1 + HD;              // 128
    float* s_nb2  = s_cb1 + HD;              // 64
    float* s_ew1  = s_nb2 + ND;              // 32
    float* s_eb1  = s_ew1 + ED;              // 32
    float* s_eb2  = s_eb1 + ED;              // 32

    const int tid = threadIdx.x;
    // W1 transposed: s[j][k]
    for (int idx = tid; idx < MI * HD; idx += THREADS) {
        int k = idx / HD, j = idx % HD;
        s_nw1t[j * PAD1 + k] = node_w1[idx];
        s_cw1t[j * PAD1 + k] = coord_w1[idx];
    }
    // W2 transposed: s[j][h]
    for (int idx = tid; idx < HD * ND; idx += THREADS) {
        int hh = idx / ND, j = idx % ND;
        s_nw2t[j * PAD2 + hh] = node_w2[idx];
    }
    for (int i = tid; i < ED * ED; i += THREADS) s_ew2[i] = edge_w2[i];
    if (tid < HD) {
        s_cw2[tid] = coord_w2[tid];
        s_nb1[tid] = node_b1[tid];
        s_cb1[tid] = coord_b1[tid];
    }
    if (tid < ND) s_nb2[tid] = node_b2[tid];
    if (tid < ED) {
        s_ew1[tid] = edge_w1[tid];
        s_eb1[tid] = edge_b1[tid];
        s_eb2[tid] = edge_b2[tid];
    }
    __syncthreads();

    const int lane = tid & 31;
    const int warp = tid >> 5;
    const int gwarp = blockIdx.x * NWARPS + warp;
    const int nwarps_total = gridDim.x * NWARPS;
    const int ntasks = N_EDGES / EB;  // 1.6M divisible by 8: no tail

    float* out_h = out;
    float* out_x = out + (size_t)N_NODES * ND;

    for (int task = gwarp; task < ntasks; task += nwarps_total) {
        const int ebase = task * EB;

        int src[EB], dst[EB];
        float dist[EB];
#pragma unroll
        for (int i = 0; i < EB; i++) {
            int e = ebase + i;
            src[i] = g_src[e];
            dst[i] = g_dst[e];
            dist[i] = edge_dist[e];
        }

        // ---- issue h gathers early (overlap with edge MLP)
        float mi[EB][5];
#pragma unroll
        for (int i = 0; i < EB; i++) {
            const float* hs = h + (size_t)src[i] * ND;
            const float* hd = h + (size_t)dst[i] * ND;
            mi[i][0] = hs[lane];
            mi[i][1] = hs[32 + lane];
            mi[i][2] = hd[lane];
            mi[i][3] = hd[32 + lane];
        }

        // ---- edge MLP: silu(d*W1 + b1) @ W2 + b2  (lane = edge-dim index)
#pragma unroll
        for (int i = 0; i < EB; i++) {
            float t = silu(fmaf(dist[i], s_ew1[lane], s_eb1[lane]));
            float acc = s_eb2[lane];
#pragma unroll 8
            for (int k = 0; k < ED; k++) {
                float tv = __shfl_sync(FULLMASK, t, k);
                acc = fmaf(tv, s_ew2[k * ED + lane], acc);
            }
            mi[i][4] = acc;
        }

        // ---- hidden layers (node & coord), j = lane + 32*r
        float an[EB][4], ac[EB][4];
#pragma unroll
        for (int i = 0; i < EB; i++)
#pragma unroll
            for (int r = 0; r < 4; r++) {
                an[i][r] = s_nb1[lane + 32 * r];
                ac[i][r] = s_cb1[lane + 32 * r];
            }

#define KSTEP(KC, C)                                            \
        {                                                       \
            _Pragma("unroll")                                   \
            for (int i = 0; i < EB; i++) {                      \
                float v = __shfl_sync(FULLMASK, mi[i][seg], kk + KC); \
                an[i][0] = fmaf(v, wn0.C, an[i][0]);            \
                an[i][1] = fmaf(v, wn1.C, an[i][1]);            \
                an[i][2] = fmaf(v, wn2.C, an[i][2]);            \
                an[i][3] = fmaf(v, wn3.C, an[i][3]);            \
                ac[i][0] = fmaf(v, wc0.C, ac[i][0]);            \
                ac[i][1] = fmaf(v, wc1.C, ac[i][1]);            \
                ac[i][2] = fmaf(v, wc2.C, ac[i][2]);            \
                ac[i][3] = fmaf(v, wc3.C, ac[i][3]);            \
            }                                                   \
        }

#pragma unroll 1
        for (int kk = 0; kk < 32; kk += 4) {
#pragma unroll
            for (int seg = 0; seg < 5; seg++) {
                const int k = seg * 32 + kk;
                float4 wn0 = *(const float4*)&s_nw1t[(lane)      * PAD1 + k];
                float4 wn1 = *(const float4*)&s_nw1t[(lane + 32) * PAD1 + k];
                float4 wn2 = *(const float4*)&s_nw1t[(lane + 64) * PAD1 + k];
                float4 wn3 = *(const float4*)&s_nw1t[(lane + 96) * PAD1 + k];
                float4 wc0 = *(const float4*)&s_cw1t[(lane)      * PAD1 + k];
                float4 wc1 = *(const float4*)&s_cw1t[(lane + 32) * PAD1 + k];
                float4 wc2 = *(const float4*)&s_cw1t[(lane + 64) * PAD1 + k];
                float4 wc3 = *(const float4*)&s_cw1t[(lane + 96) * PAD1 + k];
                KSTEP(0, x)
                KSTEP(1, y)
                KSTEP(2, z)
                KSTEP(3, w)
            }
        }
#undef KSTEP

        // ---- silu in place (an -> sn, ac -> sc)
#pragma unroll
        for (int i = 0; i < EB; i++)
#pragma unroll
            for (int r = 0; r < 4; r++) {
                an[i][r] = silu(an[i][r]);
                ac[i][r] = silu(ac[i][r]);
            }

        // ---- node out: o[j], j = lane and lane+32
        float o0[EB], o1[EB];
#pragma unroll
        for (int i = 0; i < EB; i++) {
            o0[i] = s_nb2[lane];
            o1[i] = s_nb2[lane + 32];
        }

#define HSTEP(HC, C)                                            \
        {                                                       \
            _Pragma("unroll")                                   \
            for (int i = 0; i < EB; i++) {                      \
                float hv = __shfl_sync(FULLMASK, an[i][R], hb + HC); \
                o0[i] = fmaf(hv, w0.C, o0[i]);                  \
                o1[i] = fmaf(hv, w1.C, o1[i]);                  \
            }                                                   \
        }

#pragma unroll
        for (int hh = 0; hh < HD; hh += 4) {
            float4 w0 = *(const float4*)&s_nw2t[(lane)      * PAD2 + hh];
            float4 w1 = *(const float4*)&s_nw2t[(lane + 32) * PAD2 + hh];
            const int R = hh >> 5;
            const int hb = hh & 31;
            HSTEP(0, x)
            HSTEP(1, y)
            HSTEP(2, z)
            HSTEP(3, w)
        }
#undef HSTEP

        // ---- coord scalar: cw = sum_h sc[h] * coord_w2[h]  (warp reduction)
        float cw[EB];
#pragma unroll
        for (int i = 0; i < EB; i++) {
            float p = 0.0f;
#pragma unroll
            for (int r = 0; r < 4; r++)
                p = fmaf(ac[i][r], s_cw2[lane + 32 * r], p);
#pragma unroll
            for (int off = 16; off >= 1; off >>= 1)
                p += __shfl_xor_sync(FULLMASK, p, off);
            cw[i] = p;  // all lanes hold the full sum
        }

        // ---- scatter h_agg (64 floats per edge across the warp)
#pragma unroll
        for (int i = 0; i < EB; i++) {
            float* dsth = out_h + (size_t)dst[i] * ND;
            atomicAdd(dsth + lane, o0[i]);
            atomicAdd(dsth + lane + 32, o1[i]);
        }

        // ---- scatter x_agg: lanes 0..EB-1 handle one edge each
        if (lane < EB) {
            int si = src[0], di = dst[0];
            float cwi = cw[0];
#pragma unroll
            for (int q = 1; q < EB; q++) {
                if (lane == q) { si = src[q]; di = dst[q]; cwi = cw[q]; }
            }
            const float* xs = x + (size_t)si * 3;
            const float* xd = x + (size_t)di * 3;
            float dx = xs[0] - xd[0];
            float dy = xs[1] - xd[1];
            float dz = xs[2] - xd[2];
            float len = fmaxf(sqrtf(dx * dx + dy * dy + dz * dz), 1e-8f);
            float s = __fdividef(cwi, len);
            float* dstx = out_x + (size_t)di * 3;
            atomicAdd(dstx + 0, s * dx);
            atomicAdd(dstx + 1, s * dy);
            atomicAdd(dstx + 2, s * dz);
        }
    }
}

// ---------------------------------------------------------------------------
extern "C" void kernel_launch(void* const* d_in, const int* in_sizes, int n_in,
                              void* d_out, int out_size) {
    const float* h        = (const float*)d_in[0];
    const float* x        = (const float*)d_in[1];
    const void*  eidx     = d_in[2];
    const float* edist    = (const float*)d_in[3];
    const float* node_w1  = (const float*)d_in[4];
    const float* node_b1  = (const float*)d_in[5];
    const float* node_w2  = (const float*)d_in[6];
    const float* node_b2  = (const float*)d_in[7];
    const float* coord_w1 = (const float*)d_in[8];
    const float* coord_b1 = (const float*)d_in[9];
    const float* coord_w2 = (const float*)d_in[10];
    const float* edge_w1  = (const float*)d_in[11];
    const float* edge_b1  = (const float*)d_in[12];
    const float* edge_w2  = (const float*)d_in[13];
    const float* edge_b2  = (const float*)d_in[14];
    float* out = (float*)d_out;

    (void)in_sizes; (void)n_in; (void)out_size;

    detect_kernel<<<1, 32>>>((const unsigned int*)eidx);
    convert_kernel<<<(N_EDGES + 255) / 256, 256>>>(eidx);

    const int total_out = N_NODES * ND + N_NODES * 3;
    init_out_kernel<<<(total_out + 255) / 256, 256>>>(h, x, out);

    const int smem_bytes =
        (HD * PAD1 * 2 + ND * PAD2 + ED * ED + HD * 3 + ND + ED * 3) *
        (int)sizeof(float);
    cudaFuncSetAttribute(edge_kernel,
                         cudaFuncAttributeMaxDynamicSharedMemorySize, smem_bytes);

    int nsm = 148;
    cudaDeviceGetAttribute(&nsm, cudaDevAttrMultiProcessorCount, 0);

    edge_kernel<<<nsm, THREADS, smem_bytes>>>(
        h, x, edist,
        node_w1, node_b1, node_w2, node_b2,
        coord_w1, coord_b1, coord_w2,
        edge_w1, edge_b1, edge_w2, edge_b2,
        out);
}

// round 4
// speedup vs baseline: 1.3182x; 1.3182x over previous
#include <cuda_runtime.h>

#define N_NODES 50000
#define N_EDGES 1600000
#define ND 64
#define HD 128
#define ED 32
#define MI 160
#define EB 8
#define NWARPS 8
#define THREADS (NWARPS * 32)
#define PADK2 162   // float2 units per row of packed W1 (conflict-free: 162*8 % 128 = 16)
#define PADH 66     // floats per row of W2 (LDS.64 per lane, conflict-free)
#define FULLMASK 0xffffffffu

typedef unsigned long long u64;

// Scratch (no cudaMalloc allowed): packed int32 edge indices + dtype flag.
__device__ int g_is64;
__device__ int g_src[N_EDGES];
__device__ int g_dst[N_EDGES];

// ---------------------------------------------------------------------------
__global__ void detect_kernel(const unsigned int* __restrict__ w) {
    if (blockIdx.x == 0 && threadIdx.x == 0) {
        int is64 = 1;
        for (int i = 0; i < 64; i++) {
            if (w[2 * i + 1] != 0u) { is64 = 0; break; }
        }
        g_is64 = is64;
    }
}

__global__ void convert_kernel(const void* __restrict__ p) {
    int i = blockIdx.x * blockDim.x + threadIdx.x;
    if (i >= N_EDGES) return;
    if (g_is64) {
        const long long* q = (const long long*)p;
        g_src[i] = (int)q[i];
        g_dst[i] = (int)q[N_EDGES + i];
    } else {
        const int* q = (const int*)p;
        g_src[i] = q[i];
        g_dst[i] = q[N_EDGES + i];
    }
}

__global__ void init_out_kernel(const float* __restrict__ h,
                                const float* __restrict__ x,
                                float* __restrict__ out) {
    int i = blockIdx.x * blockDim.x + threadIdx.x;
    const int nh = N_NODES * ND;
    const int total = nh + N_NODES * 3;
    if (i < nh) out[i] = h[i];
    else if (i < total) out[i] = x[i - nh];
}

__device__ __forceinline__ float silu(float v) {
    return __fdividef(v, 1.0f + __expf(-v));
}

// f32x2 packed FMA: d = a*b + c elementwise on two packed fp32 (SASS FFMA2).
__device__ __forceinline__ u64 ffma2(u64 a, u64 b, u64 c) {
    u64 d;
    asm("fma.rn.f32x2 %0, %1, %2, %3;" : "=l"(d) : "l"(a), "l"(b), "l"(c));
    return d;
}
__device__ __forceinline__ u64 pack2(float x, float y) {
    u64 r;
    asm("mov.b64 %0, {%1, %2};" : "=l"(r) : "f"(x), "f"(y));
    return r;
}
__device__ __forceinline__ float2 unpack2(u64 v) {
    float2 f;
    asm("mov.b64 {%0, %1}, %2;" : "=f"(f.x), "=f"(f.y) : "l"(v));
    return f;
}

// ---------------------------------------------------------------------------
// Persistent grid, 1 CTA/SM, 8 warps, 8 edges per warp-task, f32x2 math.
// W1 stored as pre-paired float2 {W[k][j], W[k][j+32]} so FFMA2 operands load
// directly; accumulator pairs anp[p] cover j=(lane+64p, lane+96p... +32).
// Output layer pairs j=(2*lane, 2*lane+1) enabling float2 vector atomics.
// ---------------------------------------------------------------------------
__global__ void __launch_bounds__(THREADS, 1)
edge_kernel(const float* __restrict__ h, const float* __restrict__ x,
            const float* __restrict__ edge_dist,
            const float* __restrict__ node_w1, const float* __restrict__ node_b1,
            const float* __restrict__ node_w2, const float* __restrict__ node_b2,
            const float* __restrict__ coord_w1, const float* __restrict__ coord_b1,
            const float* __restrict__ coord_w2,
            const float* __restrict__ edge_w1, const float* __restrict__ edge_b1,
            const float* __restrict__ edge_w2, const float* __restrict__ edge_b2,
            float* __restrict__ out) {
    extern __shared__ float smem[];
    // paired W1 regions viewed as u64 (one float2 per element)
    u64* s_nw1p = (u64*)smem;                      // 64 * PADK2 elems
    u64* s_cw1p = s_nw1p + 64 * PADK2;             // 64 * PADK2
    float* s_nw2 = (float*)(s_cw1p + 64 * PADK2);  // 128 * PADH floats
    float* s_ew2 = s_nw2 + HD * PADH;              // 32*32
    float* s_cw2 = s_ew2 + ED * ED;                // 128
    float* s_nb1 = s_cw2 + HD;                     // 128
    float* s_cb1 = s_nb1 + HD;                     // 128
    float* s_nb2 = s_cb1 + HD;                     // 64
    float* s_ew1 = s_nb2 + ND;                     // 32
    float* s_eb1 = s_ew1 + ED;                     // 32
    float* s_eb2 = s_eb1 + ED;                     // 32

    const int tid = threadIdx.x;
    // Fill paired W1: element ((p*32+l)*PADK2 + k) = {W[k][l+64p], W[k][l+32+64p]}
    {
        float* nf = (float*)s_nw1p;
        float* cf = (float*)s_cw1p;
        for (int idx = tid; idx < MI * HD; idx += THREADS) {
            int k = idx / HD, j = idx % HD;
            int p = j >> 6;
            int jr = j & 63;
            int l = jr & 31;
            int hi = jr >> 5;  // 0 -> .x, 1 -> .y
            int off = ((p * 32 + l) * PADK2 + k) * 2 + hi;
            nf[off] = node_w1[idx];
            cf[off] = coord_w1[idx];
        }
    }
    // W2: row-major with pad (rows h, cols j)
    for (int idx = tid; idx < HD * ND; idx += THREADS) {
        int hh = idx / ND, j = idx % ND;
        s_nw2[hh * PADH + j] = node_w2[idx];
    }
    for (int i = tid; i < ED * ED; i += THREADS) s_ew2[i] = edge_w2[i];
    if (tid < HD) {
        s_cw2[tid] = coord_w2[tid];
        s_nb1[tid] = node_b1[tid];
        s_cb1[tid] = coord_b1[tid];
    }
    if (tid < ND) s_nb2[tid] = node_b2[tid];
    if (tid < ED) {
        s_ew1[tid] = edge_w1[tid];
        s_eb1[tid] = edge_b1[tid];
        s_eb2[tid] = edge_b2[tid];
    }
    __syncthreads();

    const int lane = tid & 31;
    const int warp = tid >> 5;
    const int gwarp = blockIdx.x * NWARPS + warp;
    const int nwarps_total = gridDim.x * NWARPS;
    const int ntasks = N_EDGES / EB;

    float* out_h = out;
    float* out_x = out + (size_t)N_NODES * ND;

    const u64* w1n0 = s_nw1p + (size_t)lane * PADK2;         // p=0 row
    const u64* w1n1 = s_nw1p + (size_t)(32 + lane) * PADK2;  // p=1 row
    const u64* w1c0 = s_cw1p + (size_t)lane * PADK2;
    const u64* w1c1 = s_cw1p + (size_t)(32 + lane) * PADK2;

    for (int task = gwarp; task < ntasks; task += nwarps_total) {
        const int ebase = task * EB;

        int src[EB], dst[EB];
        float dist[EB];
#pragma unroll
        for (int i = 0; i < EB; i++) {
            int e = ebase + i;
            src[i] = g_src[e];
            dst[i] = g_dst[e];
            dist[i] = edge_dist[e];
        }

        // ---- gather h early
        float mi[EB][5];
#pragma unroll
        for (int i = 0; i < EB; i++) {
            const float* hs = h + (size_t)src[i] * ND;
            const float* hd = h + (size_t)dst[i] * ND;
            mi[i][0] = hs[lane];
            mi[i][1] = hs[32 + lane];
            mi[i][2] = hd[lane];
            mi[i][3] = hd[32 + lane];
        }

        // ---- edge MLP (scalar; small)
#pragma unroll
        for (int i = 0; i < EB; i++) {
            float t = silu(fmaf(dist[i], s_ew1[lane], s_eb1[lane]));
            float acc = s_eb2[lane];
#pragma unroll 8
            for (int k = 0; k < ED; k++) {
                float tv = __shfl_sync(FULLMASK, t, k);
                acc = fmaf(tv, s_ew2[k * ED + lane], acc);
            }
            mi[i][4] = acc;
        }

        // ---- hidden layers: packed accumulators
        // anp[i][p] = {act[lane+64p], act[lane+32+64p]}
        u64 anp[EB][2], acp[EB][2];
#pragma unroll
        for (int i = 0; i < EB; i++) {
#pragma unroll
            for (int p = 0; p < 2; p++) {
                anp[i][p] = pack2(s_nb1[lane + 64 * p], s_nb1[lane + 64 * p + 32]);
                acp[i][p] = pack2(s_cb1[lane + 64 * p], s_cb1[lane + 64 * p + 32]);
            }
        }

#pragma unroll 1
        for (int kk = 0; kk < 32; kk += 2) {
#pragma unroll
            for (int seg = 0; seg < 5; seg++) {
                const int k = seg * 32 + kk;
                ulonglong2 wn0 = *(const ulonglong2*)(w1n0 + k);
                ulonglong2 wn1 = *(const ulonglong2*)(w1n1 + k);
                ulonglong2 wc0 = *(const ulonglong2*)(w1c0 + k);
                ulonglong2 wc1 = *(const ulonglong2*)(w1c1 + k);
#pragma unroll
                for (int i = 0; i < EB; i++) {
                    float v0 = __shfl_sync(FULLMASK, mi[i][seg], kk);
                    u64 d0 = pack2(v0, v0);
                    anp[i][0] = ffma2(d0, wn0.x, anp[i][0]);
                    anp[i][1] = ffma2(d0, wn1.x, anp[i][1]);
                    acp[i][0] = ffma2(d0, wc0.x, acp[i][0]);
                    acp[i][1] = ffma2(d0, wc1.x, acp[i][1]);
                }
#pragma unroll
                for (int i = 0; i < EB; i++) {
                    float v1 = __shfl_sync(FULLMASK, mi[i][seg], kk + 1);
                    u64 d1 = pack2(v1, v1);
                    anp[i][0] = ffma2(d1, wn0.y, anp[i][0]);
                    anp[i][1] = ffma2(d1, wn1.y, anp[i][1]);
                    acp[i][0] = ffma2(d1, wc0.y, acp[i][0]);
                    acp[i][1] = ffma2(d1, wc1.y, acp[i][1]);
                }
            }
        }

        // ---- unpack + silu; sn[i][r] holds act at hidden unit h = lane + 32r
        float sn[EB][4], sc[EB][4];
#pragma unroll
        for (int i = 0; i < EB; i++) {
            float2 a0 = unpack2(anp[i][0]), a1 = unpack2(anp[i][1]);
            float2 c0 = unpack2(acp[i][0]), c1 = unpack2(acp[i][1]);
            sn[i][0] = silu(a0.x); sn[i][1] = silu(a0.y);
            sn[i][2] = silu(a1.x); sn[i][3] = silu(a1.y);
            sc[i][0] = silu(c0.x); sc[i][1] = silu(c0.y);
            sc[i][2] = silu(c1.x); sc[i][3] = silu(c1.y);
        }

        // ---- node out: o pairs cover j = (2*lane, 2*lane+1)
        u64 o2[EB];
        {
            u64 binit = pack2(s_nb2[2 * lane], s_nb2[2 * lane + 1]);
#pragma unroll
            for (int i = 0; i < EB; i++) o2[i] = binit;
        }
#pragma unroll
        for (int r = 0; r < 4; r++) {
#pragma unroll 1
            for (int hb = 0; hb < 32; hb += 2) {
                const int h0 = r * 32 + hb;
                u64 wa = *(const u64*)&s_nw2[h0 * PADH + 2 * lane];
                u64 wb = *(const u64*)&s_nw2[(h0 + 1) * PADH + 2 * lane];
#pragma unroll
                for (int i = 0; i < EB; i++) {
                    float hv0 = __shfl_sync(FULLMASK, sn[i][r], hb);
                    float hv1 = __shfl_sync(FULLMASK, sn[i][r], hb + 1);
                    o2[i] = ffma2(pack2(hv0, hv0), wa, o2[i]);
                    o2[i] = ffma2(pack2(hv1, hv1), wb, o2[i]);
                }
            }
        }

        // ---- coord scalar via warp reduction
        float cw[EB];
#pragma unroll
        for (int i = 0; i < EB; i++) {
            float p = 0.0f;
#pragma unroll
            for (int r = 0; r < 4; r++)
                p = fmaf(sc[i][r], s_cw2[lane + 32 * r], p);
#pragma unroll
            for (int off = 16; off >= 1; off >>= 1)
                p += __shfl_xor_sync(FULLMASK, p, off);
            cw[i] = p;
        }

        // ---- scatter h_agg with vector atomics
#pragma unroll
        for (int i = 0; i < EB; i++) {
            float2 ov = unpack2(o2[i]);
            float2* dsth = (float2*)(out_h + (size_t)dst[i] * ND) + lane;
            atomicAdd(dsth, ov);
        }

        // ---- scatter x_agg: lanes 0..EB-1, one edge each
        if (lane < EB) {
            int si = src[0], di = dst[0];
            float cwi = cw[0];
#pragma unroll
            for (int q = 1; q < EB; q++) {
                if (lane == q) { si = src[q]; di = dst[q]; cwi = cw[q]; }
            }
            const float* xs = x + (size_t)si * 3;
            const float* xd = x + (size_t)di * 3;
            float dx = xs[0] - xd[0];
            float dy = xs[1] - xd[1];
            float dz = xs[2] - xd[2];
            float len = fmaxf(sqrtf(dx * dx + dy * dy + dz * dz), 1e-8f);
            float s = __fdividef(cwi, len);
            float* dstx = out_x + (size_t)di * 3;
            atomicAdd(dstx + 0, s * dx);
            atomicAdd(dstx + 1, s * dy);
            atomicAdd(dstx + 2, s * dz);
        }
    }
}

// ---------------------------------------------------------------------------
extern "C" void kernel_launch(void* const* d_in, const int* in_sizes, int n_in,
                              void* d_out, int out_size) {
    const float* h        = (const float*)d_in[0];
    const float* x        = (const float*)d_in[1];
    const void*  eidx     = d_in[2];
    const float* edist    = (const float*)d_in[3];
    const float* node_w1  = (const float*)d_in[4];
    const float* node_b1  = (const float*)d_in[5];
    const float* node_w2  = (const float*)d_in[6];
    const float* node_b2  = (const float*)d_in[7];
    const float* coord_w1 = (const float*)d_in[8];
    const float* coord_b1 = (const float*)d_in[9];
    const float* coord_w2 = (const float*)d_in[10];
    const float* edge_w1  = (const float*)d_in[11];
    const float* edge_b1  = (const float*)d_in[12];
    const float* edge_w2  = (const float*)d_in[13];
    const float* edge_b2  = (const float*)d_in[14];
    float* out = (float*)d_out;

    (void)in_sizes; (void)n_in; (void)out_size;

    detect_kernel<<<1, 32>>>((const unsigned int*)eidx);
    convert_kernel<<<(N_EDGES + 255) / 256, 256>>>(eidx);

    const int total_out = N_NODES * ND + N_NODES * 3;
    init_out_kernel<<<(total_out + 255) / 256, 256>>>(h, x, out);

    const int smem_bytes =
        64 * PADK2 * 8 * 2 +                       // paired nw1 + cw1 (u64 each)
        (HD * PADH + ED * ED + HD * 3 + ND + ED * 3) * (int)sizeof(float);
    cudaFuncSetAttribute(edge_kernel,
                         cudaFuncAttributeMaxDynamicSharedMemorySize, smem_bytes);

    int nsm = 148;
    cudaDeviceGetAttribute(&nsm, cudaDevAttrMultiProcessorCount, 0);

    edge_kernel<<<nsm, THREADS, smem_bytes>>>(
        h, x, edist,
        node_w1, node_b1, node_w2, node_b2,
        coord_w1, coord_b1, coord_w2,
        edge_w1, edge_b1, edge_w2, edge_b2,
        out);
}